// round 1
// baseline (speedup 1.0000x reference)
#include <cuda_runtime.h>
#include <cuda_bf16.h>
#include <cstdint>

// Problem constants
static constexpr int O_DIM = 4096;     // out features (N)
static constexpr int I_DIM = 4096;     // in features (K)
static constexpr int M_DIM = 8 * 2048; // batch*seq (M)
static constexpr int R_DIM = 16;       // LoRA rank

// Scratch: split-precision operands (device globals — no allocation allowed)
__device__ __align__(16) __nv_bfloat16 g_Wh[(size_t)O_DIM * I_DIM];
__device__ __align__(16) __nv_bfloat16 g_Wl[(size_t)O_DIM * I_DIM];
__device__ __align__(16) __nv_bfloat16 g_Xh[(size_t)M_DIM * I_DIM];
__device__ __align__(16) __nv_bfloat16 g_Xl[(size_t)M_DIM * I_DIM];

// ---------------------------------------------------------------------------
// Kernel 1: build W = scales*(q-128) + 0.5 * up@down, split into hi/lo bf16.
// One block per output row o. down[r][i] columns are coalesced across threads;
// down (256KB) stays L2-resident across all 4096 blocks.
// ---------------------------------------------------------------------------
__global__ void prep_w_kernel(const int* __restrict__ qw,
                              const float* __restrict__ scales,
                              const float* __restrict__ up,
                              const float* __restrict__ down) {
    const int o = blockIdx.x;
    __shared__ float up_s[R_DIM];
    if (threadIdx.x < R_DIM) up_s[threadIdx.x] = up[o * R_DIM + threadIdx.x];
    __syncthreads();
    for (int i = threadIdx.x; i < I_DIM; i += blockDim.x) {
        const float q = (float)qw[(size_t)o * I_DIM + i];
        const float sc = scales[o * (I_DIM / 32) + (i >> 5)];
        float l = 0.f;
#pragma unroll
        for (int r = 0; r < R_DIM; r++) l = fmaf(up_s[r], down[r * I_DIM + i], l);
        const float w = sc * (q - 128.0f) + 0.5f * l;
        const __nv_bfloat16 h = __float2bfloat16(w);
        const float lo = w - __bfloat162float(h);
        const size_t idx = (size_t)o * I_DIM + i;
        g_Wh[idx] = h;
        g_Wl[idx] = __float2bfloat16(lo);
    }
}

// ---------------------------------------------------------------------------
// Kernel 2: split x (fp32) into hi/lo bf16, vectorized float4 in / uint2 out.
// ---------------------------------------------------------------------------
__global__ void prep_x_kernel(const float* __restrict__ x) {
    const size_t idx = (size_t)blockIdx.x * blockDim.x + threadIdx.x;
    if (idx >= (size_t)M_DIM * I_DIM / 4) return;
    const float4 v = ((const float4*)x)[idx];
    float f[4] = {v.x, v.y, v.z, v.w};
    union { __nv_bfloat16 b[4]; uint2 u; } H, L;
#pragma unroll
    for (int j = 0; j < 4; j++) {
        H.b[j] = __float2bfloat16(f[j]);
        L.b[j] = __float2bfloat16(f[j] - __bfloat162float(H.b[j]));
    }
    ((uint2*)g_Xh)[idx] = H.u;
    ((uint2*)g_Xl)[idx] = L.u;
}

// ---------------------------------------------------------------------------
// Kernel 3: GEMM  out[M][N] = Xsplit @ Wsplit^T + bias
// 128x128x32 block tile, 8 warps (warp tile 32x64), 2-stage cp.async pipeline.
// 3 MMA chains per tile pair: xh*wh + xh*wl + xl*wh  (split-bf16 precision).
// ---------------------------------------------------------------------------
static constexpr int BM = 128, BN = 128, BK = 32;
static constexpr int KT = I_DIM / BK;          // 128 K-tiles
static constexpr int TILE_BYTES = BM * 64;     // 8192 B per buffer (row = 64B)
static constexpr int STAGE_BYTES = 4 * TILE_BYTES;   // Ah, Al, Bh, Bl
static constexpr int SMEM_BYTES = 2 * STAGE_BYTES;   // 65536

__device__ __forceinline__ uint32_t cvta_smem(const void* p) {
    return (uint32_t)__cvta_generic_to_shared(p);
}
__device__ __forceinline__ void cp_async16(uint32_t s, const void* g) {
    asm volatile("cp.async.cg.shared.global [%0], [%1], 16;" :: "r"(s), "l"(g));
}
__device__ __forceinline__ void ldsm4(uint32_t (&r)[4], uint32_t addr) {
    asm volatile("ldmatrix.sync.aligned.m8n8.x4.shared.b16 {%0,%1,%2,%3}, [%4];"
                 : "=r"(r[0]), "=r"(r[1]), "=r"(r[2]), "=r"(r[3]) : "r"(addr));
}
__device__ __forceinline__ void mma16816(float (&d)[4], const uint32_t (&a)[4],
                                         uint32_t b0, uint32_t b1) {
    asm volatile(
        "mma.sync.aligned.m16n8k16.row.col.f32.bf16.bf16.f32 "
        "{%0,%1,%2,%3}, {%4,%5,%6,%7}, {%8,%9}, {%0,%1,%2,%3};"
        : "+f"(d[0]), "+f"(d[1]), "+f"(d[2]), "+f"(d[3])
        : "r"(a[0]), "r"(a[1]), "r"(a[2]), "r"(a[3]), "r"(b0), "r"(b1));
}

// Swizzle: 16B chunk c (0..3) in 64B row -> physical chunk c ^ ((row>>1)&3).
// Gives all-distinct bank groups for any 8 consecutive rows at fixed c.
__device__ __forceinline__ uint32_t swz(int row, int c) {
    return (uint32_t)(row * 64 + ((c ^ ((row >> 1) & 3)) << 4));
}

__global__ __launch_bounds__(256, 2)
void gemm_kernel(const float* __restrict__ bias, float* __restrict__ out) {
    extern __shared__ __align__(16) uint8_t smem[];
    const int tid  = threadIdx.x;
    const int lane = tid & 31;
    const int warp = tid >> 5;
    const int wm = warp >> 1;   // 0..3 (M)
    const int wn = warp & 1;    // 0..1 (N)
    const int m0 = blockIdx.y * BM;
    const int n0 = blockIdx.x * BN;

    const __nv_bfloat16* aH = g_Xh + (size_t)m0 * I_DIM;
    const __nv_bfloat16* aL = g_Xl + (size_t)m0 * I_DIM;
    const __nv_bfloat16* bH = g_Wh + (size_t)n0 * I_DIM;
    const __nv_bfloat16* bL = g_Wl + (size_t)n0 * I_DIM;

    const uint32_t sbase = cvta_smem(smem);

    // Loader geometry: 512 16B-chunks per buffer; thread covers rows r0 and r0+64.
    const int ldRow = tid >> 2;   // 0..63
    const int ldC   = tid & 3;
    const uint32_t so0 = swz(ldRow, ldC);
    const uint32_t so1 = swz(ldRow + 64, ldC);
    const size_t g0 = (size_t)ldRow * I_DIM + ldC * 8;
    const size_t g1 = (size_t)(ldRow + 64) * I_DIM + ldC * 8;

    float acc[2][8][4];
#pragma unroll
    for (int a = 0; a < 2; a++)
#pragma unroll
        for (int b = 0; b < 8; b++)
#pragma unroll
            for (int c = 0; c < 4; c++) acc[a][b][c] = 0.f;

#define LOAD_STAGE(K0, STG) do {                                              \
        const uint32_t sb = sbase + (STG) * STAGE_BYTES;                      \
        cp_async16(sb + 0 * TILE_BYTES + so0, aH + g0 + (K0));                \
        cp_async16(sb + 0 * TILE_BYTES + so1, aH + g1 + (K0));                \
        cp_async16(sb + 1 * TILE_BYTES + so0, aL + g0 + (K0));                \
        cp_async16(sb + 1 * TILE_BYTES + so1, aL + g1 + (K0));                \
        cp_async16(sb + 2 * TILE_BYTES + so0, bH + g0 + (K0));                \
        cp_async16(sb + 2 * TILE_BYTES + so1, bH + g1 + (K0));                \
        cp_async16(sb + 3 * TILE_BYTES + so0, bL + g0 + (K0));                \
        cp_async16(sb + 3 * TILE_BYTES + so1, bL + g1 + (K0));                \
        asm volatile("cp.async.commit_group;");                               \
    } while (0)

    LOAD_STAGE(0, 0);

    for (int kt = 0; kt < KT; kt++) {
        asm volatile("cp.async.wait_group 0;");
        __syncthreads();
        if (kt + 1 < KT) LOAD_STAGE((kt + 1) * BK, (kt + 1) & 1);

        const uint32_t sb  = sbase + (kt & 1) * STAGE_BYTES;
        const uint32_t aHb = sb + 0 * TILE_BYTES;
        const uint32_t aLb = sb + 1 * TILE_BYTES;
        const uint32_t bHb = sb + 2 * TILE_BYTES;
        const uint32_t bLb = sb + 3 * TILE_BYTES;

#pragma unroll
        for (int ks = 0; ks < 2; ks++) {
            uint32_t ah[2][4], al[2][4];
#pragma unroll
            for (int mt = 0; mt < 2; mt++) {
                const int r = wm * 32 + mt * 16 + (lane & 15);
                const int c = ks * 2 + (lane >> 4);
                const uint32_t off = swz(r, c);
                ldsm4(ah[mt], aHb + off);
                ldsm4(al[mt], aLb + off);
            }
#pragma unroll
            for (int np = 0; np < 4; np++) {
                const int r = wn * 64 + np * 16 + (lane & 7) + ((lane >> 4) << 3);
                const int c = ks * 2 + ((lane >> 3) & 1);
                const uint32_t off = swz(r, c);
                uint32_t bh[4], bl[4];
                ldsm4(bh, bHb + off);
                ldsm4(bl, bLb + off);
#pragma unroll
                for (int mt = 0; mt < 2; mt++) {
                    mma16816(acc[mt][np * 2 + 0], ah[mt], bh[0], bh[1]);
                    mma16816(acc[mt][np * 2 + 0], ah[mt], bl[0], bl[1]);
                    mma16816(acc[mt][np * 2 + 0], al[mt], bh[0], bh[1]);
                    mma16816(acc[mt][np * 2 + 1], ah[mt], bh[2], bh[3]);
                    mma16816(acc[mt][np * 2 + 1], ah[mt], bl[2], bl[3]);
                    mma16816(acc[mt][np * 2 + 1], al[mt], bh[2], bh[3]);
                }
            }
        }
        __syncthreads();
    }
#undef LOAD_STAGE

    // Epilogue: + bias, fp32 out, float2 stores
#pragma unroll
    for (int mt = 0; mt < 2; mt++) {
#pragma unroll
        for (int nt = 0; nt < 8; nt++) {
            const int row = m0 + wm * 32 + mt * 16 + (lane >> 2);
            const int col = n0 + wn * 64 + nt * 8 + (lane & 3) * 2;
            const float b0 = bias[col], b1 = bias[col + 1];
            float2 v0 = {acc[mt][nt][0] + b0, acc[mt][nt][1] + b1};
            float2 v1 = {acc[mt][nt][2] + b0, acc[mt][nt][3] + b1};
            *(float2*)(out + (size_t)row * O_DIM + col) = v0;
            *(float2*)(out + (size_t)(row + 8) * O_DIM + col) = v1;
        }
    }
}

// ---------------------------------------------------------------------------
extern "C" void kernel_launch(void* const* d_in, const int* in_sizes, int n_in,
                              void* d_out, int out_size) {
    const int*   qweight   = (const int*)d_in[0];
    const float* scales    = (const float*)d_in[1];
    const float* lora_up   = (const float*)d_in[2];
    const float* lora_down = (const float*)d_in[3];
    const float* bias      = (const float*)d_in[4];
    const float* x         = (const float*)d_in[5];
    float* out = (float*)d_out;

    prep_w_kernel<<<O_DIM, 256>>>(qweight, scales, lora_up, lora_down);

    const size_t n4 = (size_t)M_DIM * I_DIM / 4;
    prep_x_kernel<<<(unsigned)((n4 + 255) / 256), 256>>>(x);

    cudaFuncSetAttribute(gemm_kernel,
                         cudaFuncAttributeMaxDynamicSharedMemorySize, SMEM_BYTES);
    dim3 grid(O_DIM / BN, M_DIM / BM);  // (32, 128)
    gemm_kernel<<<grid, 256, SMEM_BYTES>>>(bias, out);
}